// round 14
// baseline (speedup 1.0000x reference)
#include <cuda_runtime.h>
#include <cuda_bf16.h>
#include <cuda_fp16.h>
#include <cuda_fp8.h>
#include <cstdint>
#include <math.h>

// Problem constants (B=2,H=8,N=2048,D=128)
#define BHN 16
#define SEQ 2048
#define DH  128
#define NQB (SEQ/64)
#define NKB (SEQ/128)
#define NT  (SEQ/64)     // 32 kv tiles total
#define NTH 16           // tiles per split-K half

// ---------------- scratch ----------------
__device__ __align__(16) int8_t g_q8[BHN*SEQ*DH];
__device__ __align__(16) int8_t g_k8[BHN*SEQ*DH];
__device__ __align__(16) __half g_vh[(size_t)BHN*SEQ*DH];
__device__ float g_qscale[BHN*NQB];
__device__ float g_kscale[BHN*NKB];
__device__ float g_vsf[BHN*SEQ];
__device__ float g_kpart[BHN][16][DH];
// split-K partials
__device__ __align__(16) float g_po[2][(size_t)BHN*SEQ*DH];
__device__ float g_pm[2][BHN*SEQ];
__device__ float g_pl[2][BHN*SEQ];

// ================= preprocessing =================

__global__ void nq_kmean_part(const float* __restrict__ k) {
    int bh = blockIdx.x >> 4;
    int ch = blockIdx.x & 15;
    int d  = threadIdx.x;
    const float* p = k + ((size_t)bh*SEQ + (size_t)ch*128)*DH + d;
    float s0=0.f, s1=0.f, s2=0.f, s3=0.f;
    #pragma unroll 4
    for (int n = 0; n < 128; n += 4) {
        s0 += p[(size_t)(n+0)*DH];
        s1 += p[(size_t)(n+1)*DH];
        s2 += p[(size_t)(n+2)*DH];
        s3 += p[(size_t)(n+3)*DH];
    }
    g_kpart[bh][ch][d] = (s0+s1)+(s2+s3);
}

__global__ void nq_qqv(const float* __restrict__ q, const float* __restrict__ v) {
    if (blockIdx.x < BHN*NQB) {
        int bh = blockIdx.x / NQB;
        int qb = blockIdx.x % NQB;
        const float* src = q + ((size_t)bh*SEQ + (size_t)qb*64)*DH;
        int8_t*      dst = g_q8 + ((size_t)bh*SEQ + (size_t)qb*64)*DH;

        __shared__ float part[256];
        float am = 0.f;
        for (int i = threadIdx.x; i < 64*DH; i += 256) am = fmaxf(am, fabsf(src[i]));
        part[threadIdx.x] = am;
        __syncthreads();
        for (int s = 128; s > 0; s >>= 1) {
            if (threadIdx.x < s) part[threadIdx.x] = fmaxf(part[threadIdx.x], part[threadIdx.x + s]);
            __syncthreads();
        }
        const float scale = part[0] / 127.0f;
        if (threadIdx.x == 0) g_qscale[bh*NQB + qb] = scale;

        for (int i = threadIdx.x; i < 64*DH; i += 256) {
            int vq = 0;
            if (scale > 0.f) {
                float r = src[i] / scale;
                vq = (int)r;
                if (vq < -128) vq = -128;
                if (vq >  127) vq =  127;
            }
            dst[i] = (int8_t)vq;
        }
    } else {
        int b  = blockIdx.x - BHN*NQB;
        int bh = b >> 8;
        int tb = b & 255;
        int warp = threadIdx.x >> 5;
        int lane = threadIdx.x & 31;
        int token = tb*8 + warp;

        const float* src = v + ((size_t)bh*SEQ + token)*DH + lane*4;
        float4 x = *reinterpret_cast<const float4*>(src);
        float amax = fmaxf(fmaxf(fabsf(x.x), fabsf(x.y)), fmaxf(fabsf(x.z), fabsf(x.w)));
        #pragma unroll
        for (int o = 16; o; o >>= 1) amax = fmaxf(amax, __shfl_xor_sync(0xffffffffu, amax, o));
        float sf = amax / 448.0f;
        if (lane == 0) g_vsf[bh*SEQ + token] = sf;
        float den = (sf > 0.f) ? sf : 1.f;

        __half h[4];
        #pragma unroll
        for (int i = 0; i < 4; i++) {
            float raw = ((&x.x)[i]) / den;
            __nv_fp8_storage_t s = __nv_cvt_float_to_fp8(raw, __NV_SATFINITE, __NV_E4M3);
            __half_raw hr = __nv_cvt_fp8_to_halfraw(s, __NV_E4M3);
            h[i] = *reinterpret_cast<__half*>(&hr);
        }
        __half2 h01 = __halves2half2(h[0], h[1]);
        __half2 h23 = __halves2half2(h[2], h[3]);
        uint2 pack;
        pack.x = *reinterpret_cast<uint32_t*>(&h01);
        pack.y = *reinterpret_cast<uint32_t*>(&h23);
        *reinterpret_cast<uint2*>(&g_vh[((size_t)bh*SEQ + token)*DH + lane*4]) = pack;
    }
}

__global__ void nq_quant_k(const float* __restrict__ k) {
    int bh = blockIdx.x / NKB;
    int kb = blockIdx.x % NKB;
    const float* src = k + ((size_t)bh*SEQ + (size_t)kb*128)*DH;
    int8_t*      dst = g_k8 + ((size_t)bh*SEQ + (size_t)kb*128)*DH;

    __shared__ float mu[DH];
    __shared__ float part[128];
    {
        float s = 0.f;
        #pragma unroll
        for (int c = 0; c < 16; c++) s += g_kpart[bh][c][threadIdx.x];
        mu[threadIdx.x] = s / (float)SEQ;
    }
    __syncthreads();

    float am = 0.f;
    for (int i = threadIdx.x; i < 128*DH; i += 128) {
        float x = src[i] - mu[i % DH];
        am = fmaxf(am, fabsf(x));
    }
    part[threadIdx.x] = am;
    __syncthreads();
    for (int s = 64; s > 0; s >>= 1) {
        if (threadIdx.x < s) part[threadIdx.x] = fmaxf(part[threadIdx.x], part[threadIdx.x + s]);
        __syncthreads();
    }
    const float scale = part[0] / 127.0f;
    if (threadIdx.x == 0) g_kscale[bh*NKB + kb] = scale;

    for (int i = threadIdx.x; i < 128*DH; i += 128) {
        int vq = 0;
        if (scale > 0.f) {
            float x = src[i] - mu[i % DH];
            float r = x / scale;
            vq = (int)r;
            if (vq < -128) vq = -128;
            if (vq >  127) vq =  127;
        }
        dst[i] = (int8_t)vq;
    }
}

// ================= fused flash attention (split-K x2) =================

__device__ __forceinline__ void ldsm_x4(uint32_t addr, uint32_t& r0, uint32_t& r1,
                                        uint32_t& r2, uint32_t& r3) {
    asm volatile("ldmatrix.sync.aligned.m8n8.x4.shared.b16 {%0,%1,%2,%3}, [%4];\n"
                 : "=r"(r0), "=r"(r1), "=r"(r2), "=r"(r3) : "r"(addr));
}
__device__ __forceinline__ void ldsm_x4_trans(uint32_t addr, uint32_t& r0, uint32_t& r1,
                                              uint32_t& r2, uint32_t& r3) {
    asm volatile("ldmatrix.sync.aligned.m8n8.x4.trans.shared.b16 {%0,%1,%2,%3}, [%4];\n"
                 : "=r"(r0), "=r"(r1), "=r"(r2), "=r"(r3) : "r"(addr));
}
__device__ __forceinline__ void cpa16(uint32_t dst, const void* src) {
    asm volatile("cp.async.cg.shared.global [%0], [%1], 16;\n" :: "r"(dst), "l"(src));
}
__device__ __forceinline__ void cpa_commit() {
    asm volatile("cp.async.commit_group;\n");
}
__device__ __forceinline__ uint32_t pkf16(float hi, float lo) {
    uint32_t r;
    asm("cvt.rn.f16x2.f32 %0, %1, %2;" : "=r"(r) : "f"(hi), "f"(lo));
    return r;
}
__device__ __forceinline__ float bf16r(float x) {
    return __bfloat162float(__float2bfloat16_rn(x));
}

#define VSTRIDE  136
#define SK_BYTES 9216
#define SV_BYTES 17408
#define OFF_K0   0
#define OFF_V0   18432
#define OFF_SF0  53248
#define OFF_KS   53760
#define SMEM_TOT 53824

__global__ __launch_bounds__(128, 4) void attn_kernel() {
    const int bx   = blockIdx.x;
    const int bh   = bx >> 6;
    const int qt   = (bx >> 1) & 31;
    const int half = bx & 1;
    const int base = half * NTH;
    const int tid = threadIdx.x;
    const int warp = tid >> 5, lane = tid & 31;
    const int gi = lane >> 2, ti = lane & 3;

    __shared__ __align__(128) char smem[SMEM_TOT];
    const uint32_t sb = (uint32_t)__cvta_generic_to_shared(smem);

    // ---- Q tile: synchronous load into (future) K0 region ----
    {
        const int4* qsrc = reinterpret_cast<const int4*>(g_q8 + ((size_t)bh*SEQ + (size_t)qt*64)*DH);
        #pragma unroll
        for (int i = 0; i < 4; i++) {
            int id = tid + i*128;
            int row = id >> 3, c = id & 7;
            *reinterpret_cast<int4*>(&smem[OFF_K0 + row*144 + c*16]) = qsrc[id];
        }
    }
    const float qscale = g_qscale[bh*NQB + qt];
    if (tid < 16) *reinterpret_cast<float*>(&smem[OFF_KS + tid*4]) = g_kscale[bh*NKB + tid];
    __syncthreads();

    uint32_t qa[4][4];
    {
        const char* sQ = smem + OFF_K0;
        const int r0 = (warp*16 + gi)*144;
        const int r1 = (warp*16 + gi + 8)*144;
        #pragma unroll
        for (int kc = 0; kc < 4; kc++) {
            qa[kc][0] = *reinterpret_cast<const uint32_t*>(&sQ[r0 + kc*32 + ti*4]);
            qa[kc][1] = *reinterpret_cast<const uint32_t*>(&sQ[r1 + kc*32 + ti*4]);
            qa[kc][2] = *reinterpret_cast<const uint32_t*>(&sQ[r0 + kc*32 + 16 + ti*4]);
            qa[kc][3] = *reinterpret_cast<const uint32_t*>(&sQ[r1 + kc*32 + 16 + ti*4]);
        }
    }
    __syncthreads();   // done reading Q -> safe to overwrite with K

    const int8_t* kbase  = g_k8 + (size_t)bh*SEQ*DH;
    const __half* vbase  = g_vh + (size_t)bh*SEQ*DH;
    const float* vsfbase = g_vsf + (size_t)bh*SEQ;
    const float qsl = qscale * 0.08838834764831845f * 1.4426950408889634f;

    auto issue_tile = [&](int t, int b) {
        const int n0 = t*64;
        const uint32_t kb = sb + OFF_K0 + b*SK_BYTES;
        const uint32_t vb = sb + OFF_V0 + b*SV_BYTES;
        const uint32_t fb = sb + OFF_SF0 + b*256;
        const int8_t* kg = kbase + (size_t)n0*DH;
        const __half* vg = vbase + (size_t)n0*DH;
        #pragma unroll
        for (int i = 0; i < 4; i++) {
            int id = tid + i*128;
            int row = id >> 3, c = id & 7;
            cpa16(kb + row*144 + c*16, kg + (size_t)id*16);
        }
        #pragma unroll
        for (int i = 0; i < 8; i++) {
            int id = tid + i*128;
            int row = id >> 4, c = id & 15;
            cpa16(vb + row*(VSTRIDE*2) + c*16, vg + (size_t)id*8);
        }
        if (tid < 16) cpa16(fb + tid*16, vsfbase + n0 + tid*4);
        cpa_commit();
    };

    issue_tile(base + 0, 0);
    issue_tile(base + 1, 1);

    float oacc[16][4];
    #pragma unroll
    for (int i = 0; i < 16; i++)
        #pragma unroll
        for (int j = 0; j < 4; j++) oacc[i][j] = 0.f;
    float m0 = -INFINITY, m1 = -INFINITY, l0 = 0.f, l1 = 0.f;

    const int mQK = lane >> 3, rQK = lane & 7;
    const uint32_t qkLane = (uint32_t)(((mQK >> 1)*8 + rQK)*144 + (mQK & 1)*16);
    const int lrow = lane & 15;
    const int lsel = lane >> 4;

    for (int it = 0; it < NTH; it++) {
        const int t = base + it;
        const int buf = it & 1;
        if (it < NTH-1) asm volatile("cp.async.wait_group 1;\n");
        else            asm volatile("cp.async.wait_group 0;\n");
        __syncthreads();

        const uint32_t skbuf = sb + OFF_K0 + buf*SK_BYTES;
        const uint32_t svbuf = sb + OFF_V0 + buf*SV_BYTES;
        const float* vsf = reinterpret_cast<const float*>(smem + OFF_SF0 + buf*256);
        const float sall2 = qsl * reinterpret_cast<const float*>(smem + OFF_KS)[t >> 1];

        // -------- QK --------
        int sacc[8][4];
        #pragma unroll
        for (int j = 0; j < 8; j++)
            #pragma unroll
            for (int x = 0; x < 4; x++) sacc[j][x] = 0;

        #pragma unroll
        for (int kc = 0; kc < 4; kc++) {
            #pragma unroll
            for (int p = 0; p < 4; p++) {
                uint32_t b0, b1, b2, b3;
                ldsm_x4(skbuf + qkLane + (uint32_t)(p*2304 + kc*32), b0, b1, b2, b3);
                asm volatile(
                    "mma.sync.aligned.m16n8k32.row.col.s32.s8.s8.s32 "
                    "{%0,%1,%2,%3},{%4,%5,%6,%7},{%8,%9},{%0,%1,%2,%3};\n"
                    : "+r"(sacc[2*p][0]), "+r"(sacc[2*p][1]), "+r"(sacc[2*p][2]), "+r"(sacc[2*p][3])
                    : "r"(qa[kc][0]), "r"(qa[kc][1]), "r"(qa[kc][2]), "r"(qa[kc][3]),
                      "r"(b0), "r"(b1));
                asm volatile(
                    "mma.sync.aligned.m16n8k32.row.col.s32.s8.s8.s32 "
                    "{%0,%1,%2,%3},{%4,%5,%6,%7},{%8,%9},{%0,%1,%2,%3};\n"
                    : "+r"(sacc[2*p+1][0]), "+r"(sacc[2*p+1][1]), "+r"(sacc[2*p+1][2]), "+r"(sacc[2*p+1][3])
                    : "r"(qa[kc][0]), "r"(qa[kc][1]), "r"(qa[kc][2]), "r"(qa[kc][3]),
                      "r"(b2), "r"(b3));
            }
        }

        // -------- online softmax (log2 domain, integer max) --------
        int im0 = sacc[0][0], im1 = sacc[0][2];
        #pragma unroll
        for (int j = 0; j < 8; j++) {
            im0 = max(im0, max(sacc[j][0], sacc[j][1]));
            im1 = max(im1, max(sacc[j][2], sacc[j][3]));
        }
        im0 = max(im0, __shfl_xor_sync(0xffffffffu, im0, 1));
        im0 = max(im0, __shfl_xor_sync(0xffffffffu, im0, 2));
        im1 = max(im1, __shfl_xor_sync(0xffffffffu, im1, 1));
        im1 = max(im1, __shfl_xor_sync(0xffffffffu, im1, 2));
        const float mn0 = fmaxf(m0, (float)im0 * sall2);
        const float mn1 = fmaxf(m1, (float)im1 * sall2);
        const float c0 = exp2f(m0 - mn0), c1 = exp2f(m1 - mn1);
        m0 = mn0; m1 = mn1;
        l0 *= c0;  l1 *= c1;
        if (__any_sync(0xffffffffu, (c0 < 1.0f) | (c1 < 1.0f))) {
            #pragma unroll
            for (int dn = 0; dn < 16; dn++) {
                oacc[dn][0] *= c0; oacc[dn][1] *= c0;
                oacc[dn][2] *= c1; oacc[dn][3] *= c1;
            }
        }

        // P fragments: hi + residual fp16, vsf folded in
        uint32_t pa1[4][4], pa2[4][4];
        #pragma unroll
        for (int j = 0; j < 8; j++) {
            float e0 = exp2f(fmaf((float)sacc[j][0], sall2, -mn0));
            float e1 = exp2f(fmaf((float)sacc[j][1], sall2, -mn0));
            float e2 = exp2f(fmaf((float)sacc[j][2], sall2, -mn1));
            float e3 = exp2f(fmaf((float)sacc[j][3], sall2, -mn1));
            l0 += e0 + e1;  l1 += e2 + e3;
            const float vs0 = vsf[j*8 + ti*2];
            const float vs1 = vsf[j*8 + ti*2 + 1];
            float s0 = e0*vs0, s1 = e1*vs1, s2 = e2*vs0, s3 = e3*vs1;
            uint32_t h01 = pkf16(s1, s0);
            uint32_t h23 = pkf16(s3, s2);
            float2 f01 = __half22float2(*reinterpret_cast<__half2*>(&h01));
            float2 f23 = __half22float2(*reinterpret_cast<__half2*>(&h23));
            uint32_t r01 = pkf16(s1 - f01.y, s0 - f01.x);
            uint32_t r23 = pkf16(s3 - f23.y, s2 - f23.x);
            int kc = j >> 1, lo = (j & 1) * 2;
            pa1[kc][lo]   = h01;
            pa1[kc][lo+1] = h23;
            pa2[kc][lo]   = r01;
            pa2[kc][lo+1] = r23;
        }

        // -------- PV --------
        #pragma unroll
        for (int kc = 0; kc < 4; kc++) {
            #pragma unroll
            for (int mI = 0; mI < 8; mI++) {
                uint32_t addr = svbuf + (uint32_t)(((kc*16 + lrow)*VSTRIDE + (2*mI + lsel)*8) * 2);
                uint32_t b0, b1, b2, b3;
                ldsm_x4_trans(addr, b0, b1, b2, b3);
                const int dn0 = 2*mI, dn1 = 2*mI + 1;
                asm volatile(
                    "mma.sync.aligned.m16n8k16.row.col.f32.f16.f16.f32 "
                    "{%0,%1,%2,%3},{%4,%5,%6,%7},{%8,%9},{%0,%1,%2,%3};\n"
                    : "+f"(oacc[dn0][0]), "+f"(oacc[dn0][1]), "+f"(oacc[dn0][2]), "+f"(oacc[dn0][3])
                    : "r"(pa1[kc][0]), "r"(pa1[kc][1]), "r"(pa1[kc][2]), "r"(pa1[kc][3]),
                      "r"(b0), "r"(b1));
                asm volatile(
                    "mma.sync.aligned.m16n8k16.row.col.f32.f16.f16.f32 "
                    "{%0,%1,%2,%3},{%4,%5,%6,%7},{%8,%9},{%0,%1,%2,%3};\n"
                    : "+f"(oacc[dn0][0]), "+f"(oacc[dn0][1]), "+f"(oacc[dn0][2]), "+f"(oacc[dn0][3])
                    : "r"(pa2[kc][0]), "r"(pa2[kc][1]), "r"(pa2[kc][2]), "r"(pa2[kc][3]),
                      "r"(b0), "r"(b1));
                asm volatile(
                    "mma.sync.aligned.m16n8k16.row.col.f32.f16.f16.f32 "
                    "{%0,%1,%2,%3},{%4,%5,%6,%7},{%8,%9},{%0,%1,%2,%3};\n"
                    : "+f"(oacc[dn1][0]), "+f"(oacc[dn1][1]), "+f"(oacc[dn1][2]), "+f"(oacc[dn1][3])
                    : "r"(pa1[kc][0]), "r"(pa1[kc][1]), "r"(pa1[kc][2]), "r"(pa1[kc][3]),
                      "r"(b2), "r"(b3));
                asm volatile(
                    "mma.sync.aligned.m16n8k16.row.col.f32.f16.f16.f32 "
                    "{%0,%1,%2,%3},{%4,%5,%6,%7},{%8,%9},{%0,%1,%2,%3};\n"
                    : "+f"(oacc[dn1][0]), "+f"(oacc[dn1][1]), "+f"(oacc[dn1][2]), "+f"(oacc[dn1][3])
                    : "r"(pa2[kc][0]), "r"(pa2[kc][1]), "r"(pa2[kc][2]), "r"(pa2[kc][3]),
                      "r"(b2), "r"(b3));
            }
        }

        __syncthreads();
        if (it + 2 < NTH) issue_tile(t + 2, buf);
    }

    // -------- epilogue: write split-K partials --------
    l0 += __shfl_xor_sync(0xffffffffu, l0, 1);
    l0 += __shfl_xor_sync(0xffffffffu, l0, 2);
    l1 += __shfl_xor_sync(0xffffffffu, l1, 1);
    l1 += __shfl_xor_sync(0xffffffffu, l1, 2);
    const int r0 = qt*64 + warp*16 + gi;
    const int r1 = r0 + 8;
    const size_t row0 = (size_t)bh*SEQ + r0;
    const size_t row1 = (size_t)bh*SEQ + r1;
    if (ti == 0) {
        g_pm[half][row0] = m0;  g_pl[half][row0] = l0;
        g_pm[half][row1] = m1;  g_pl[half][row1] = l1;
    }
    float* o0 = g_po[half] + row0*DH;
    float* o1 = g_po[half] + row1*DH;
    #pragma unroll
    for (int dn = 0; dn < 16; dn++) {
        int col = dn*8 + ti*2;
        float2 pLo, pHi;
        pLo.x = oacc[dn][0]; pLo.y = oacc[dn][1];
        pHi.x = oacc[dn][2]; pHi.y = oacc[dn][3];
        *reinterpret_cast<float2*>(o0 + col) = pLo;
        *reinterpret_cast<float2*>(o1 + col) = pHi;
    }
}

// ================= split-K merge =================
__global__ __launch_bounds__(256) void merge_kernel(float* __restrict__ out) {
    const size_t row = (size_t)blockIdx.x*8 + (threadIdx.x >> 5);   // over BHN*SEQ
    const int lane = threadIdx.x & 31;
    const float ma = g_pm[0][row], mb = g_pm[1][row];
    const float la = g_pl[0][row], lb = g_pl[1][row];
    const float m  = fmaxf(ma, mb);
    const float fa = exp2f(ma - m), fb = exp2f(mb - m);
    const float inv = 1.f / (la*fa + lb*fb);
    const float4 a = *reinterpret_cast<const float4*>(g_po[0] + row*DH + lane*4);
    const float4 b = *reinterpret_cast<const float4*>(g_po[1] + row*DH + lane*4);
    float4 r;
    r.x = bf16r((a.x*fa + b.x*fb) * inv);
    r.y = bf16r((a.y*fa + b.y*fb) * inv);
    r.z = bf16r((a.z*fa + b.z*fb) * inv);
    r.w = bf16r((a.w*fa + b.w*fb) * inv);
    *reinterpret_cast<float4*>(out + row*DH + lane*4) = r;
}

// ---------------- launch ----------------
extern "C" void kernel_launch(void* const* d_in, const int* in_sizes, int n_in,
                              void* d_out, int out_size) {
    const float* q = (const float*)d_in[0];
    const float* k = (const float*)d_in[1];
    const float* v = (const float*)d_in[2];
    float* out = (float*)d_out;

    nq_kmean_part<<<BHN*16, 128>>>(k);
    nq_qqv<<<BHN*NQB + BHN*256, 256>>>(q, v);
    nq_quant_k<<<BHN*NKB, 128>>>(k);
    attn_kernel<<<BHN*NQB*2, 128>>>();       // 4th launch (profiled)
    merge_kernel<<<(BHN*SEQ)/8, 256>>>(out);
}

// round 16
// speedup vs baseline: 1.0391x; 1.0391x over previous
#include <cuda_runtime.h>
#include <cuda_bf16.h>
#include <cuda_fp16.h>
#include <cuda_fp8.h>
#include <cstdint>
#include <math.h>

// Problem constants (B=2,H=8,N=2048,D=128)
#define BHN 16
#define SEQ 2048
#define DH  128
#define NQB (SEQ/64)
#define NKB (SEQ/128)
#define NSPLIT 4
#define NTH  8           // tiles per split-K quarter

// ---------------- scratch ----------------
__device__ __align__(16) int8_t g_q8[BHN*SEQ*DH];
__device__ __align__(16) int8_t g_k8[BHN*SEQ*DH];
__device__ __align__(16) __half g_vh[(size_t)BHN*SEQ*DH];
__device__ float g_qscale[BHN*NQB];
__device__ float g_kscale[BHN*NKB];
__device__ float g_vsf[BHN*SEQ];
__device__ float g_kpart[BHN][16][DH];
// split-K partials
__device__ __align__(16) float g_po[NSPLIT][(size_t)BHN*SEQ*DH];
__device__ float g_pm[NSPLIT][BHN*SEQ];
__device__ float g_pl[NSPLIT][BHN*SEQ];

// ================= preprocessing =================

__global__ void nq_kmean_part(const float* __restrict__ k) {
    int bh = blockIdx.x >> 4;
    int ch = blockIdx.x & 15;
    int d  = threadIdx.x;
    const float* p = k + ((size_t)bh*SEQ + (size_t)ch*128)*DH + d;
    float s0=0.f, s1=0.f, s2=0.f, s3=0.f;
    #pragma unroll 4
    for (int n = 0; n < 128; n += 4) {
        s0 += p[(size_t)(n+0)*DH];
        s1 += p[(size_t)(n+1)*DH];
        s2 += p[(size_t)(n+2)*DH];
        s3 += p[(size_t)(n+3)*DH];
    }
    g_kpart[bh][ch][d] = (s0+s1)+(s2+s3);
}

// merged q-quant (blocks [0,BHN*NQB)) + v-quant, vectorized
__global__ void nq_qqv(const float* __restrict__ q, const float* __restrict__ v) {
    if (blockIdx.x < BHN*NQB) {
        int bh = blockIdx.x / NQB;
        int qb = blockIdx.x % NQB;
        const float4* src4 = reinterpret_cast<const float4*>(q + ((size_t)bh*SEQ + (size_t)qb*64)*DH);
        char4* dst4 = reinterpret_cast<char4*>(g_q8 + ((size_t)bh*SEQ + (size_t)qb*64)*DH);

        __shared__ float part[256];
        float am = 0.f;
        #pragma unroll
        for (int i = threadIdx.x; i < 2048; i += 256) {
            float4 x = src4[i];
            am = fmaxf(am, fmaxf(fmaxf(fabsf(x.x), fabsf(x.y)), fmaxf(fabsf(x.z), fabsf(x.w))));
        }
        part[threadIdx.x] = am;
        __syncthreads();
        for (int s = 128; s > 0; s >>= 1) {
            if (threadIdx.x < s) part[threadIdx.x] = fmaxf(part[threadIdx.x], part[threadIdx.x + s]);
            __syncthreads();
        }
        const float scale = part[0] / 127.0f;
        if (threadIdx.x == 0) g_qscale[bh*NQB + qb] = scale;

        #pragma unroll
        for (int i = threadIdx.x; i < 2048; i += 256) {
            float4 x = src4[i];
            char4 c = make_char4(0,0,0,0);
            if (scale > 0.f) {
                int a0 = (int)(x.x/scale), a1 = (int)(x.y/scale);
                int a2 = (int)(x.z/scale), a3 = (int)(x.w/scale);
                c.x = (char)max(-128, min(127, a0));
                c.y = (char)max(-128, min(127, a1));
                c.z = (char)max(-128, min(127, a2));
                c.w = (char)max(-128, min(127, a3));
            }
            dst4[i] = c;
        }
    } else {
        int b  = blockIdx.x - BHN*NQB;
        int bh = b >> 8;
        int tb = b & 255;
        int warp = threadIdx.x >> 5;
        int lane = threadIdx.x & 31;
        int token = tb*8 + warp;

        const float* src = v + ((size_t)bh*SEQ + token)*DH + lane*4;
        float4 x = *reinterpret_cast<const float4*>(src);
        float amax = fmaxf(fmaxf(fabsf(x.x), fabsf(x.y)), fmaxf(fabsf(x.z), fabsf(x.w)));
        #pragma unroll
        for (int o = 16; o; o >>= 1) amax = fmaxf(amax, __shfl_xor_sync(0xffffffffu, amax, o));
        float sf = amax / 448.0f;
        if (lane == 0) g_vsf[bh*SEQ + token] = sf;
        float den = (sf > 0.f) ? sf : 1.f;

        __half h[4];
        #pragma unroll
        for (int i = 0; i < 4; i++) {
            float raw = ((&x.x)[i]) / den;
            __nv_fp8_storage_t s = __nv_cvt_float_to_fp8(raw, __NV_SATFINITE, __NV_E4M3);
            __half_raw hr = __nv_cvt_fp8_to_halfraw(s, __NV_E4M3);
            h[i] = *reinterpret_cast<__half*>(&hr);
        }
        __half2 h01 = __halves2half2(h[0], h[1]);
        __half2 h23 = __halves2half2(h[2], h[3]);
        uint2 pack;
        pack.x = *reinterpret_cast<uint32_t*>(&h01);
        pack.y = *reinterpret_cast<uint32_t*>(&h23);
        *reinterpret_cast<uint2*>(&g_vh[((size_t)bh*SEQ + token)*DH + lane*4]) = pack;
    }
}

__global__ void nq_quant_k(const float* __restrict__ k) {
    int bh = blockIdx.x / NKB;
    int kb = blockIdx.x % NKB;
    const float4* src4 = reinterpret_cast<const float4*>(k + ((size_t)bh*SEQ + (size_t)kb*128)*DH);
    char4* dst4 = reinterpret_cast<char4*>(g_k8 + ((size_t)bh*SEQ + (size_t)kb*128)*DH);

    __shared__ float mu[DH];
    __shared__ float part[128];
    {
        float s = 0.f;
        #pragma unroll
        for (int c = 0; c < 16; c++) s += g_kpart[bh][c][threadIdx.x];
        mu[threadIdx.x] = s / (float)SEQ;
    }
    __syncthreads();
    const float4* mu4 = reinterpret_cast<const float4*>(mu);

    float am = 0.f;
    #pragma unroll
    for (int i = threadIdx.x; i < 4096; i += 128) {
        float4 x = src4[i];
        float4 m = mu4[i & 31];
        am = fmaxf(am, fmaxf(fmaxf(fabsf(x.x-m.x), fabsf(x.y-m.y)),
                             fmaxf(fabsf(x.z-m.z), fabsf(x.w-m.w))));
    }
    part[threadIdx.x] = am;
    __syncthreads();
    for (int s = 64; s > 0; s >>= 1) {
        if (threadIdx.x < s) part[threadIdx.x] = fmaxf(part[threadIdx.x], part[threadIdx.x + s]);
        __syncthreads();
    }
    const float scale = part[0] / 127.0f;
    if (threadIdx.x == 0) g_kscale[bh*NKB + kb] = scale;

    #pragma unroll
    for (int i = threadIdx.x; i < 4096; i += 128) {
        float4 x = src4[i];
        float4 m = mu4[i & 31];
        char4 c = make_char4(0,0,0,0);
        if (scale > 0.f) {
            int a0 = (int)((x.x-m.x)/scale), a1 = (int)((x.y-m.y)/scale);
            int a2 = (int)((x.z-m.z)/scale), a3 = (int)((x.w-m.w)/scale);
            c.x = (char)max(-128, min(127, a0));
            c.y = (char)max(-128, min(127, a1));
            c.z = (char)max(-128, min(127, a2));
            c.w = (char)max(-128, min(127, a3));
        }
        dst4[i] = c;
    }
}

// ================= fused flash attention (split-K x4) =================

__device__ __forceinline__ void ldsm_x4(uint32_t addr, uint32_t& r0, uint32_t& r1,
                                        uint32_t& r2, uint32_t& r3) {
    asm volatile("ldmatrix.sync.aligned.m8n8.x4.shared.b16 {%0,%1,%2,%3}, [%4];\n"
                 : "=r"(r0), "=r"(r1), "=r"(r2), "=r"(r3) : "r"(addr));
}
__device__ __forceinline__ void ldsm_x4_trans(uint32_t addr, uint32_t& r0, uint32_t& r1,
                                              uint32_t& r2, uint32_t& r3) {
    asm volatile("ldmatrix.sync.aligned.m8n8.x4.trans.shared.b16 {%0,%1,%2,%3}, [%4];\n"
                 : "=r"(r0), "=r"(r1), "=r"(r2), "=r"(r3) : "r"(addr));
}
__device__ __forceinline__ void cpa16(uint32_t dst, const void* src) {
    asm volatile("cp.async.cg.shared.global [%0], [%1], 16;\n" :: "r"(dst), "l"(src));
}
__device__ __forceinline__ void cpa_commit() {
    asm volatile("cp.async.commit_group;\n");
}
__device__ __forceinline__ uint32_t pkf16(float hi, float lo) {
    uint32_t r;
    asm("cvt.rn.f16x2.f32 %0, %1, %2;" : "=r"(r) : "f"(hi), "f"(lo));
    return r;
}
__device__ __forceinline__ float bf16r(float x) {
    return __bfloat162float(__float2bfloat16_rn(x));
}

#define VSTRIDE  136
#define SK_BYTES 9216
#define SV_BYTES 17408
#define OFF_K0   0
#define OFF_V0   18432
#define OFF_SF0  53248
#define OFF_KS   53760
#define SMEM_TOT 53824

__global__ __launch_bounds__(128, 4) void attn_kernel() {
    const int bx   = blockIdx.x;
    const int bh   = bx >> 7;
    const int qt   = (bx >> 2) & 31;
    const int part = bx & 3;
    const int base = part * NTH;
    const int tid = threadIdx.x;
    const int warp = tid >> 5, lane = tid & 31;
    const int gi = lane >> 2, ti = lane & 3;

    __shared__ __align__(128) char smem[SMEM_TOT];
    const uint32_t sb = (uint32_t)__cvta_generic_to_shared(smem);

    // ---- Q tile: synchronous load into (future) K0 region ----
    {
        const int4* qsrc = reinterpret_cast<const int4*>(g_q8 + ((size_t)bh*SEQ + (size_t)qt*64)*DH);
        #pragma unroll
        for (int i = 0; i < 4; i++) {
            int id = tid + i*128;
            int row = id >> 3, c = id & 7;
            *reinterpret_cast<int4*>(&smem[OFF_K0 + row*144 + c*16]) = qsrc[id];
        }
    }
    const float qscale = g_qscale[bh*NQB + qt];
    if (tid < 16) *reinterpret_cast<float*>(&smem[OFF_KS + tid*4]) = g_kscale[bh*NKB + tid];
    __syncthreads();

    uint32_t qa[4][4];
    {
        const char* sQ = smem + OFF_K0;
        const int r0 = (warp*16 + gi)*144;
        const int r1 = (warp*16 + gi + 8)*144;
        #pragma unroll
        for (int kc = 0; kc < 4; kc++) {
            qa[kc][0] = *reinterpret_cast<const uint32_t*>(&sQ[r0 + kc*32 + ti*4]);
            qa[kc][1] = *reinterpret_cast<const uint32_t*>(&sQ[r1 + kc*32 + ti*4]);
            qa[kc][2] = *reinterpret_cast<const uint32_t*>(&sQ[r0 + kc*32 + 16 + ti*4]);
            qa[kc][3] = *reinterpret_cast<const uint32_t*>(&sQ[r1 + kc*32 + 16 + ti*4]);
        }
    }
    __syncthreads();   // done reading Q -> safe to overwrite with K

    const int8_t* kbase  = g_k8 + (size_t)bh*SEQ*DH;
    const __half* vbase  = g_vh + (size_t)bh*SEQ*DH;
    const float* vsfbase = g_vsf + (size_t)bh*SEQ;
    const float qsl = qscale * 0.08838834764831845f * 1.4426950408889634f;

    auto issue_tile = [&](int t, int b) {
        const int n0 = t*64;
        const uint32_t kb = sb + OFF_K0 + b*SK_BYTES;
        const uint32_t vb = sb + OFF_V0 + b*SV_BYTES;
        const uint32_t fb = sb + OFF_SF0 + b*256;
        const int8_t* kg = kbase + (size_t)n0*DH;
        const __half* vg = vbase + (size_t)n0*DH;
        #pragma unroll
        for (int i = 0; i < 4; i++) {
            int id = tid + i*128;
            int row = id >> 3, c = id & 7;
            cpa16(kb + row*144 + c*16, kg + (size_t)id*16);
        }
        #pragma unroll
        for (int i = 0; i < 8; i++) {
            int id = tid + i*128;
            int row = id >> 4, c = id & 15;
            cpa16(vb + row*(VSTRIDE*2) + c*16, vg + (size_t)id*8);
        }
        if (tid < 16) cpa16(fb + tid*16, vsfbase + n0 + tid*4);
        cpa_commit();
    };

    issue_tile(base + 0, 0);
    issue_tile(base + 1, 1);

    float oacc[16][4];
    #pragma unroll
    for (int i = 0; i < 16; i++)
        #pragma unroll
        for (int j = 0; j < 4; j++) oacc[i][j] = 0.f;
    float m0 = -INFINITY, m1 = -INFINITY, l0 = 0.f, l1 = 0.f;

    const int mQK = lane >> 3, rQK = lane & 7;
    const uint32_t qkLane = (uint32_t)(((mQK >> 1)*8 + rQK)*144 + (mQK & 1)*16);
    const int lrow = lane & 15;
    const int lsel = lane >> 4;

    for (int it = 0; it < NTH; it++) {
        const int t = base + it;
        const int buf = it & 1;
        if (it < NTH-1) asm volatile("cp.async.wait_group 1;\n");
        else            asm volatile("cp.async.wait_group 0;\n");
        __syncthreads();

        const uint32_t skbuf = sb + OFF_K0 + buf*SK_BYTES;
        const uint32_t svbuf = sb + OFF_V0 + buf*SV_BYTES;
        const float* vsf = reinterpret_cast<const float*>(smem + OFF_SF0 + buf*256);
        const float sall2 = qsl * reinterpret_cast<const float*>(smem + OFF_KS)[t >> 1];

        // -------- QK --------
        int sacc[8][4];
        #pragma unroll
        for (int j = 0; j < 8; j++)
            #pragma unroll
            for (int x = 0; x < 4; x++) sacc[j][x] = 0;

        #pragma unroll
        for (int kc = 0; kc < 4; kc++) {
            #pragma unroll
            for (int p = 0; p < 4; p++) {
                uint32_t b0, b1, b2, b3;
                ldsm_x4(skbuf + qkLane + (uint32_t)(p*2304 + kc*32), b0, b1, b2, b3);
                asm volatile(
                    "mma.sync.aligned.m16n8k32.row.col.s32.s8.s8.s32 "
                    "{%0,%1,%2,%3},{%4,%5,%6,%7},{%8,%9},{%0,%1,%2,%3};\n"
                    : "+r"(sacc[2*p][0]), "+r"(sacc[2*p][1]), "+r"(sacc[2*p][2]), "+r"(sacc[2*p][3])
                    : "r"(qa[kc][0]), "r"(qa[kc][1]), "r"(qa[kc][2]), "r"(qa[kc][3]),
                      "r"(b0), "r"(b1));
                asm volatile(
                    "mma.sync.aligned.m16n8k32.row.col.s32.s8.s8.s32 "
                    "{%0,%1,%2,%3},{%4,%5,%6,%7},{%8,%9},{%0,%1,%2,%3};\n"
                    : "+r"(sacc[2*p+1][0]), "+r"(sacc[2*p+1][1]), "+r"(sacc[2*p+1][2]), "+r"(sacc[2*p+1][3])
                    : "r"(qa[kc][0]), "r"(qa[kc][1]), "r"(qa[kc][2]), "r"(qa[kc][3]),
                      "r"(b2), "r"(b3));
            }
        }

        // -------- online softmax (log2 domain, integer max) --------
        int im0 = sacc[0][0], im1 = sacc[0][2];
        #pragma unroll
        for (int j = 0; j < 8; j++) {
            im0 = max(im0, max(sacc[j][0], sacc[j][1]));
            im1 = max(im1, max(sacc[j][2], sacc[j][3]));
        }
        im0 = max(im0, __shfl_xor_sync(0xffffffffu, im0, 1));
        im0 = max(im0, __shfl_xor_sync(0xffffffffu, im0, 2));
        im1 = max(im1, __shfl_xor_sync(0xffffffffu, im1, 1));
        im1 = max(im1, __shfl_xor_sync(0xffffffffu, im1, 2));
        const float mn0 = fmaxf(m0, (float)im0 * sall2);
        const float mn1 = fmaxf(m1, (float)im1 * sall2);
        const float c0 = exp2f(m0 - mn0), c1 = exp2f(m1 - mn1);
        m0 = mn0; m1 = mn1;
        l0 *= c0;  l1 *= c1;
        if (__any_sync(0xffffffffu, (c0 < 1.0f) | (c1 < 1.0f))) {
            #pragma unroll
            for (int dn = 0; dn < 16; dn++) {
                oacc[dn][0] *= c0; oacc[dn][1] *= c0;
                oacc[dn][2] *= c1; oacc[dn][3] *= c1;
            }
        }

        // P fragments: hi + residual fp16, vsf folded in
        uint32_t pa1[4][4], pa2[4][4];
        #pragma unroll
        for (int j = 0; j < 8; j++) {
            float e0 = exp2f(fmaf((float)sacc[j][0], sall2, -mn0));
            float e1 = exp2f(fmaf((float)sacc[j][1], sall2, -mn0));
            float e2 = exp2f(fmaf((float)sacc[j][2], sall2, -mn1));
            float e3 = exp2f(fmaf((float)sacc[j][3], sall2, -mn1));
            l0 += e0 + e1;  l1 += e2 + e3;
            const float vs0 = vsf[j*8 + ti*2];
            const float vs1 = vsf[j*8 + ti*2 + 1];
            float s0 = e0*vs0, s1 = e1*vs1, s2 = e2*vs0, s3 = e3*vs1;
            uint32_t h01 = pkf16(s1, s0);
            uint32_t h23 = pkf16(s3, s2);
            float2 f01 = __half22float2(*reinterpret_cast<__half2*>(&h01));
            float2 f23 = __half22float2(*reinterpret_cast<__half2*>(&h23));
            uint32_t r01 = pkf16(s1 - f01.y, s0 - f01.x);
            uint32_t r23 = pkf16(s3 - f23.y, s2 - f23.x);
            int kc = j >> 1, lo = (j & 1) * 2;
            pa1[kc][lo]   = h01;
            pa1[kc][lo+1] = h23;
            pa2[kc][lo]   = r01;
            pa2[kc][lo+1] = r23;
        }

        // -------- PV --------
        #pragma unroll
        for (int kc = 0; kc < 4; kc++) {
            #pragma unroll
            for (int mI = 0; mI < 8; mI++) {
                uint32_t addr = svbuf + (uint32_t)(((kc*16 + lrow)*VSTRIDE + (2*mI + lsel)*8) * 2);
                uint32_t b0, b1, b2, b3;
                ldsm_x4_trans(addr, b0, b1, b2, b3);
                const int dn0 = 2*mI, dn1 = 2*mI + 1;
                asm volatile(
                    "mma.sync.aligned.m16n8k16.row.col.f32.f16.f16.f32 "
                    "{%0,%1,%2,%3},{%4,%5,%6,%7},{%8,%9},{%0,%1,%2,%3};\n"
                    : "+f"(oacc[dn0][0]), "+f"(oacc[dn0][1]), "+f"(oacc[dn0][2]), "+f"(oacc[dn0][3])
                    : "r"(pa1[kc][0]), "r"(pa1[kc][1]), "r"(pa1[kc][2]), "r"(pa1[kc][3]),
                      "r"(b0), "r"(b1));
                asm volatile(
                    "mma.sync.aligned.m16n8k16.row.col.f32.f16.f16.f32 "
                    "{%0,%1,%2,%3},{%4,%5,%6,%7},{%8,%9},{%0,%1,%2,%3};\n"
                    : "+f"(oacc[dn0][0]), "+f"(oacc[dn0][1]), "+f"(oacc[dn0][2]), "+f"(oacc[dn0][3])
                    : "r"(pa2[kc][0]), "r"(pa2[kc][1]), "r"(pa2[kc][2]), "r"(pa2[kc][3]),
                      "r"(b0), "r"(b1));
                asm volatile(
                    "mma.sync.aligned.m16n8k16.row.col.f32.f16.f16.f32 "
                    "{%0,%1,%2,%3},{%4,%5,%6,%7},{%8,%9},{%0,%1,%2,%3};\n"
                    : "+f"(oacc[dn1][0]), "+f"(oacc[dn1][1]), "+f"(oacc[dn1][2]), "+f"(oacc[dn1][3])
                    : "r"(pa1[kc][0]), "r"(pa1[kc][1]), "r"(pa1[kc][2]), "r"(pa1[kc][3]),
                      "r"(b2), "r"(b3));
                asm volatile(
                    "mma.sync.aligned.m16n8k16.row.col.f32.f16.f16.f32 "
                    "{%0,%1,%2,%3},{%4,%5,%6,%7},{%8,%9},{%0,%1,%2,%3};\n"
                    : "+f"(oacc[dn1][0]), "+f"(oacc[dn1][1]), "+f"(oacc[dn1][2]), "+f"(oacc[dn1][3])
                    : "r"(pa2[kc][0]), "r"(pa2[kc][1]), "r"(pa2[kc][2]), "r"(pa2[kc][3]),
                      "r"(b2), "r"(b3));
            }
        }

        __syncthreads();
        if (it + 2 < NTH) issue_tile(t + 2, buf);
    }

    // -------- epilogue: write split-K partials --------
    l0 += __shfl_xor_sync(0xffffffffu, l0, 1);
    l0 += __shfl_xor_sync(0xffffffffu, l0, 2);
    l1 += __shfl_xor_sync(0xffffffffu, l1, 1);
    l1 += __shfl_xor_sync(0xffffffffu, l1, 2);
    const int r0 = qt*64 + warp*16 + gi;
    const int r1 = r0 + 8;
    const size_t row0 = (size_t)bh*SEQ + r0;
    const size_t row1 = (size_t)bh*SEQ + r1;
    if (ti == 0) {
        g_pm[part][row0] = m0;  g_pl[part][row0] = l0;
        g_pm[part][row1] = m1;  g_pl[part][row1] = l1;
    }
    float* o0 = g_po[part] + row0*DH;
    float* o1 = g_po[part] + row1*DH;
    #pragma unroll
    for (int dn = 0; dn < 16; dn++) {
        int col = dn*8 + ti*2;
        float2 pLo, pHi;
        pLo.x = oacc[dn][0]; pLo.y = oacc[dn][1];
        pHi.x = oacc[dn][2]; pHi.y = oacc[dn][3];
        *reinterpret_cast<float2*>(o0 + col) = pLo;
        *reinterpret_cast<float2*>(o1 + col) = pHi;
    }
}

// ================= split-K merge (4-way) =================
__global__ __launch_bounds__(256) void merge_kernel(float* __restrict__ out) {
    const size_t row = (size_t)blockIdx.x*8 + (threadIdx.x >> 5);   // over BHN*SEQ
    const int lane = threadIdx.x & 31;
    float mm = g_pm[0][row];
    #pragma unroll
    for (int p = 1; p < NSPLIT; p++) mm = fmaxf(mm, g_pm[p][row]);
    float f[NSPLIT];
    float lsum = 0.f;
    #pragma unroll
    for (int p = 0; p < NSPLIT; p++) {
        f[p] = exp2f(g_pm[p][row] - mm);
        lsum += g_pl[p][row] * f[p];
    }
    const float inv = 1.f / lsum;
    float4 acc = make_float4(0.f, 0.f, 0.f, 0.f);
    #pragma unroll
    for (int p = 0; p < NSPLIT; p++) {
        const float4 a = *reinterpret_cast<const float4*>(g_po[p] + row*DH + lane*4);
        acc.x = fmaf(a.x, f[p], acc.x);
        acc.y = fmaf(a.y, f[p], acc.y);
        acc.z = fmaf(a.z, f[p], acc.z);
        acc.w = fmaf(a.w, f[p], acc.w);
    }
    float4 r;
    r.x = bf16r(acc.x * inv);
    r.y = bf16r(acc.y * inv);
    r.z = bf16r(acc.z * inv);
    r.w = bf16r(acc.w * inv);
    *reinterpret_cast<float4*>(out + row*DH + lane*4) = r;
}

// ---------------- launch ----------------
extern "C" void kernel_launch(void* const* d_in, const int* in_sizes, int n_in,
                              void* d_out, int out_size) {
    const float* q = (const float*)d_in[0];
    const float* k = (const float*)d_in[1];
    const float* v = (const float*)d_in[2];
    float* out = (float*)d_out;

    nq_kmean_part<<<BHN*16, 128>>>(k);
    nq_qqv<<<BHN*NQB + BHN*256, 256>>>(q, v);
    nq_quant_k<<<BHN*NKB, 128>>>(k);
    attn_kernel<<<BHN*NQB*NSPLIT, 128>>>();   // 4th launch (profiled)
    merge_kernel<<<(BHN*SEQ)/8, 256>>>(out);
}

// round 17
// speedup vs baseline: 1.0625x; 1.0225x over previous
#include <cuda_runtime.h>
#include <cuda_bf16.h>
#include <cuda_fp16.h>
#include <cuda_fp8.h>
#include <cstdint>
#include <math.h>

// Problem constants (B=2,H=8,N=2048,D=128)
#define BHN 16
#define SEQ 2048
#define DH  128
#define NQB (SEQ/64)
#define NKB (SEQ/128)
#define NSPLIT 4
#define NTH  8           // tiles per split-K quarter

// ---------------- scratch ----------------
__device__ __align__(16) int8_t g_q8[BHN*SEQ*DH];
__device__ __align__(16) int8_t g_k8[BHN*SEQ*DH];
__device__ __align__(16) __half g_vh[(size_t)BHN*SEQ*DH];
__device__ float g_qscale[BHN*NQB];
__device__ float g_kscale[BHN*NKB];
__device__ float g_vsf[BHN*SEQ];
__device__ float g_kpart[BHN][16][DH];
__device__ __align__(16) float g_po[NSPLIT][(size_t)BHN*SEQ*DH];
__device__ float g_pm[NSPLIT][BHN*SEQ];
__device__ float g_pl[NSPLIT][BHN*SEQ];

// ================= preprocessing (merged: q-quant | v-quant | k-mean) =================
__global__ void nq_pre(const float* __restrict__ q, const float* __restrict__ v,
                       const float* __restrict__ k) {
    if (blockIdx.x < BHN*NQB) {
        int bh = blockIdx.x / NQB;
        int qb = blockIdx.x % NQB;
        const float4* src4 = reinterpret_cast<const float4*>(q + ((size_t)bh*SEQ + (size_t)qb*64)*DH);
        char4* dst4 = reinterpret_cast<char4*>(g_q8 + ((size_t)bh*SEQ + (size_t)qb*64)*DH);

        __shared__ float part[256];
        float am = 0.f;
        #pragma unroll
        for (int i = threadIdx.x; i < 2048; i += 256) {
            float4 x = src4[i];
            am = fmaxf(am, fmaxf(fmaxf(fabsf(x.x), fabsf(x.y)), fmaxf(fabsf(x.z), fabsf(x.w))));
        }
        part[threadIdx.x] = am;
        __syncthreads();
        for (int s = 128; s > 0; s >>= 1) {
            if (threadIdx.x < s) part[threadIdx.x] = fmaxf(part[threadIdx.x], part[threadIdx.x + s]);
            __syncthreads();
        }
        const float scale = part[0] / 127.0f;
        if (threadIdx.x == 0) g_qscale[bh*NQB + qb] = scale;

        #pragma unroll
        for (int i = threadIdx.x; i < 2048; i += 256) {
            float4 x = src4[i];
            char4 c = make_char4(0,0,0,0);
            if (scale > 0.f) {
                int a0 = (int)(x.x/scale), a1 = (int)(x.y/scale);
                int a2 = (int)(x.z/scale), a3 = (int)(x.w/scale);
                c.x = (char)max(-128, min(127, a0));
                c.y = (char)max(-128, min(127, a1));
                c.z = (char)max(-128, min(127, a2));
                c.w = (char)max(-128, min(127, a3));
            }
            dst4[i] = c;
        }
    } else if (blockIdx.x < BHN*NQB + BHN*256) {
        int b  = blockIdx.x - BHN*NQB;
        int bh = b >> 8;
        int tb = b & 255;
        int warp = threadIdx.x >> 5;
        int lane = threadIdx.x & 31;
        int token = tb*8 + warp;

        const float* src = v + ((size_t)bh*SEQ + token)*DH + lane*4;
        float4 x = *reinterpret_cast<const float4*>(src);
        float amax = fmaxf(fmaxf(fabsf(x.x), fabsf(x.y)), fmaxf(fabsf(x.z), fabsf(x.w)));
        #pragma unroll
        for (int o = 16; o; o >>= 1) amax = fmaxf(amax, __shfl_xor_sync(0xffffffffu, amax, o));
        float sf = amax / 448.0f;
        if (lane == 0) g_vsf[bh*SEQ + token] = sf;
        float den = (sf > 0.f) ? sf : 1.f;

        __half h[4];
        #pragma unroll
        for (int i = 0; i < 4; i++) {
            float raw = ((&x.x)[i]) / den;
            __nv_fp8_storage_t s = __nv_cvt_float_to_fp8(raw, __NV_SATFINITE, __NV_E4M3);
            __half_raw hr = __nv_cvt_fp8_to_halfraw(s, __NV_E4M3);
            h[i] = *reinterpret_cast<__half*>(&hr);
        }
        __half2 h01 = __halves2half2(h[0], h[1]);
        __half2 h23 = __halves2half2(h[2], h[3]);
        uint2 pack;
        pack.x = *reinterpret_cast<uint32_t*>(&h01);
        pack.y = *reinterpret_cast<uint32_t*>(&h23);
        *reinterpret_cast<uint2*>(&g_vh[((size_t)bh*SEQ + token)*DH + lane*4]) = pack;
    } else {
        // k partial means (same summation order as before: 128 threads, 128 rows)
        int b  = blockIdx.x - BHN*NQB - BHN*256;
        int bh = b >> 4, ch = b & 15;
        if (threadIdx.x < 128) {
            int d = threadIdx.x;
            const float* p = k + ((size_t)bh*SEQ + (size_t)ch*128)*DH + d;
            float s0=0.f, s1=0.f, s2=0.f, s3=0.f;
            #pragma unroll 4
            for (int n = 0; n < 128; n += 4) {
                s0 += p[(size_t)(n+0)*DH];
                s1 += p[(size_t)(n+1)*DH];
                s2 += p[(size_t)(n+2)*DH];
                s3 += p[(size_t)(n+3)*DH];
            }
            g_kpart[bh][ch][d] = (s0+s1)+(s2+s3);
        }
    }
}

__global__ void nq_quant_k(const float* __restrict__ k) {
    int bh = blockIdx.x / NKB;
    int kb = blockIdx.x % NKB;
    const float4* src4 = reinterpret_cast<const float4*>(k + ((size_t)bh*SEQ + (size_t)kb*128)*DH);
    char4* dst4 = reinterpret_cast<char4*>(g_k8 + ((size_t)bh*SEQ + (size_t)kb*128)*DH);

    __shared__ float mu[DH];
    __shared__ float part[128];
    {
        float s = 0.f;
        #pragma unroll
        for (int c = 0; c < 16; c++) s += g_kpart[bh][c][threadIdx.x];
        mu[threadIdx.x] = s / (float)SEQ;
    }
    __syncthreads();
    const float4* mu4 = reinterpret_cast<const float4*>(mu);

    float am = 0.f;
    #pragma unroll
    for (int i = threadIdx.x; i < 4096; i += 128) {
        float4 x = src4[i];
        float4 m = mu4[i & 31];
        am = fmaxf(am, fmaxf(fmaxf(fabsf(x.x-m.x), fabsf(x.y-m.y)),
                             fmaxf(fabsf(x.z-m.z), fabsf(x.w-m.w))));
    }
    part[threadIdx.x] = am;
    __syncthreads();
    for (int s = 64; s > 0; s >>= 1) {
        if (threadIdx.x < s) part[threadIdx.x] = fmaxf(part[threadIdx.x], part[threadIdx.x + s]);
        __syncthreads();
    }
    const float scale = part[0] / 127.0f;
    if (threadIdx.x == 0) g_kscale[bh*NKB + kb] = scale;

    #pragma unroll
    for (int i = threadIdx.x; i < 4096; i += 128) {
        float4 x = src4[i];
        float4 m = mu4[i & 31];
        char4 c = make_char4(0,0,0,0);
        if (scale > 0.f) {
            int a0 = (int)((x.x-m.x)/scale), a1 = (int)((x.y-m.y)/scale);
            int a2 = (int)((x.z-m.z)/scale), a3 = (int)((x.w-m.w)/scale);
            c.x = (char)max(-128, min(127, a0));
            c.y = (char)max(-128, min(127, a1));
            c.z = (char)max(-128, min(127, a2));
            c.w = (char)max(-128, min(127, a3));
        }
        dst4[i] = c;
    }
}

// ================= fused flash attention (split-K x4, head-issued pipeline) =================

__device__ __forceinline__ void ldsm_x4(uint32_t addr, uint32_t& r0, uint32_t& r1,
                                        uint32_t& r2, uint32_t& r3) {
    asm volatile("ldmatrix.sync.aligned.m8n8.x4.shared.b16 {%0,%1,%2,%3}, [%4];\n"
                 : "=r"(r0), "=r"(r1), "=r"(r2), "=r"(r3) : "r"(addr));
}
__device__ __forceinline__ void ldsm_x4_trans(uint32_t addr, uint32_t& r0, uint32_t& r1,
                                              uint32_t& r2, uint32_t& r3) {
    asm volatile("ldmatrix.sync.aligned.m8n8.x4.trans.shared.b16 {%0,%1,%2,%3}, [%4];\n"
                 : "=r"(r0), "=r"(r1), "=r"(r2), "=r"(r3) : "r"(addr));
}
__device__ __forceinline__ void cpa16(uint32_t dst, const void* src) {
    asm volatile("cp.async.cg.shared.global [%0], [%1], 16;\n" :: "r"(dst), "l"(src));
}
__device__ __forceinline__ void cpa_commit() {
    asm volatile("cp.async.commit_group;\n");
}
__device__ __forceinline__ uint32_t pkf16(float hi, float lo) {
    uint32_t r;
    asm("cvt.rn.f16x2.f32 %0, %1, %2;" : "=r"(r) : "f"(hi), "f"(lo));
    return r;
}
__device__ __forceinline__ float bf16r(float x) {
    return __bfloat162float(__float2bfloat16_rn(x));
}

#define VSTRIDE  136
#define SK_BYTES 9216
#define SV_BYTES 17408
#define OFF_K    0                 // 2 K buffers
#define OFF_V    18432             // 3 V buffers
#define OFF_SF   70656             // 3 vsf buffers (256B each)
#define OFF_KS   71424
#define SMEM_TOT 71488

__global__ __launch_bounds__(128, 3) void attn_kernel() {
    extern __shared__ __align__(128) char smem[];
    const int bx   = blockIdx.x;
    const int bh   = bx >> 7;
    const int qt   = (bx >> 2) & 31;
    const int part = bx & 3;
    const int base = part * NTH;
    const int tid = threadIdx.x;
    const int warp = tid >> 5, lane = tid & 31;
    const int gi = lane >> 2, ti = lane & 3;

    const uint32_t sb = (uint32_t)__cvta_generic_to_shared(smem);

    // ---- Q tile: synchronous load into (future) K0 region ----
    {
        const int4* qsrc = reinterpret_cast<const int4*>(g_q8 + ((size_t)bh*SEQ + (size_t)qt*64)*DH);
        #pragma unroll
        for (int i = 0; i < 4; i++) {
            int id = tid + i*128;
            int row = id >> 3, c = id & 7;
            *reinterpret_cast<int4*>(&smem[OFF_K + row*144 + c*16]) = qsrc[id];
        }
    }
    const float qscale = g_qscale[bh*NQB + qt];
    if (tid < 16) *reinterpret_cast<float*>(&smem[OFF_KS + tid*4]) = g_kscale[bh*NKB + tid];
    __syncthreads();

    uint32_t qa[4][4];
    {
        const char* sQ = smem + OFF_K;
        const int r0 = (warp*16 + gi)*144;
        const int r1 = (warp*16 + gi + 8)*144;
        #pragma unroll
        for (int kc = 0; kc < 4; kc++) {
            qa[kc][0] = *reinterpret_cast<const uint32_t*>(&sQ[r0 + kc*32 + ti*4]);
            qa[kc][1] = *reinterpret_cast<const uint32_t*>(&sQ[r1 + kc*32 + ti*4]);
            qa[kc][2] = *reinterpret_cast<const uint32_t*>(&sQ[r0 + kc*32 + 16 + ti*4]);
            qa[kc][3] = *reinterpret_cast<const uint32_t*>(&sQ[r1 + kc*32 + 16 + ti*4]);
        }
    }
    __syncthreads();   // done reading Q -> safe to overwrite with K0

    const int8_t* kbase  = g_k8 + (size_t)bh*SEQ*DH;
    const __half* vbase  = g_vh + (size_t)bh*SEQ*DH;
    const float* vsfbase = g_vsf + (size_t)bh*SEQ;
    const float qsl = qscale * 0.08838834764831845f * 1.4426950408889634f;

    // issue loads for tile t into K buffer kb (0/1) and V buffer vb (0/1/2)
    auto issue_tile = [&](int t, int kb, int vb) {
        const int n0 = t*64;
        const uint32_t kdst = sb + OFF_K + kb*SK_BYTES;
        const uint32_t vdst = sb + OFF_V + vb*SV_BYTES;
        const uint32_t fdst = sb + OFF_SF + vb*256;
        const int8_t* kg = kbase + (size_t)n0*DH;
        const __half* vg = vbase + (size_t)n0*DH;
        #pragma unroll
        for (int i = 0; i < 4; i++) {
            int id = tid + i*128;
            int row = id >> 3, c = id & 7;
            cpa16(kdst + row*144 + c*16, kg + (size_t)id*16);
        }
        #pragma unroll
        for (int i = 0; i < 8; i++) {
            int id = tid + i*128;
            int row = id >> 4, c = id & 15;
            cpa16(vdst + row*(VSTRIDE*2) + c*16, vg + (size_t)id*8);
        }
        if (tid < 16) cpa16(fdst + tid*16, vsfbase + n0 + tid*4);
        cpa_commit();
    };

    float oacc[16][4];
    #pragma unroll
    for (int i = 0; i < 16; i++)
        #pragma unroll
        for (int j = 0; j < 4; j++) oacc[i][j] = 0.f;
    float m0 = -INFINITY, m1 = -INFINITY, l0 = 0.f, l1 = 0.f;

    const int mQK = lane >> 3, rQK = lane & 7;
    const uint32_t qkLane = (uint32_t)(((mQK >> 1)*8 + rQK)*144 + (mQK & 1)*16);
    const int lrow = lane & 15;
    const int lsel = lane >> 4;

    int sacc[8][4];
    auto do_qk = [&](int kb) {
        const uint32_t skbuf = sb + OFF_K + kb*SK_BYTES;
        #pragma unroll
        for (int j = 0; j < 8; j++)
            #pragma unroll
            for (int x = 0; x < 4; x++) sacc[j][x] = 0;
        #pragma unroll
        for (int kc = 0; kc < 4; kc++) {
            #pragma unroll
            for (int p = 0; p < 4; p++) {
                uint32_t b0, b1, b2, b3;
                ldsm_x4(skbuf + qkLane + (uint32_t)(p*2304 + kc*32), b0, b1, b2, b3);
                asm volatile(
                    "mma.sync.aligned.m16n8k32.row.col.s32.s8.s8.s32 "
                    "{%0,%1,%2,%3},{%4,%5,%6,%7},{%8,%9},{%0,%1,%2,%3};\n"
                    : "+r"(sacc[2*p][0]), "+r"(sacc[2*p][1]), "+r"(sacc[2*p][2]), "+r"(sacc[2*p][3])
                    : "r"(qa[kc][0]), "r"(qa[kc][1]), "r"(qa[kc][2]), "r"(qa[kc][3]),
                      "r"(b0), "r"(b1));
                asm volatile(
                    "mma.sync.aligned.m16n8k32.row.col.s32.s8.s8.s32 "
                    "{%0,%1,%2,%3},{%4,%5,%6,%7},{%8,%9},{%0,%1,%2,%3};\n"
                    : "+r"(sacc[2*p+1][0]), "+r"(sacc[2*p+1][1]), "+r"(sacc[2*p+1][2]), "+r"(sacc[2*p+1][3])
                    : "r"(qa[kc][0]), "r"(qa[kc][1]), "r"(qa[kc][2]), "r"(qa[kc][3]),
                      "r"(b2), "r"(b3));
            }
        }
    };

    // prologue
    issue_tile(base + 0, 0, 0);
    issue_tile(base + 1, 1, 1);
    asm volatile("cp.async.wait_group 0;\n");
    __syncthreads();
    do_qk(0);
    __syncthreads();   // all warps done reading K buf0 -> head of it=0 may overwrite it

    uint32_t pa1[4][4], pa2[4][4];
    int vb = 0;        // V buffer of tile `it` (cycles 0,1,2)

    for (int it = 0; it < NTH; it++) {
        // ---- head: issue tile it+2 (K buf it%2 and V buf (it+2)%3 are dead) ----
        if (it + 2 < NTH) {
            int vb2 = vb + 2; if (vb2 >= 3) vb2 -= 3;
            issue_tile(base + it + 2, it & 1, vb2);
        }

        const float* vsf = reinterpret_cast<const float*>(smem + OFF_SF + vb*256);
        const float sall2 = qsl * reinterpret_cast<const float*>(smem + OFF_KS)[(base + it) >> 1];

        // ---- A: softmax + pack(it) (consumes sacc) ----
        int im0 = sacc[0][0], im1 = sacc[0][2];
        #pragma unroll
        for (int j = 0; j < 8; j++) {
            im0 = max(im0, max(sacc[j][0], sacc[j][1]));
            im1 = max(im1, max(sacc[j][2], sacc[j][3]));
        }
        im0 = max(im0, __shfl_xor_sync(0xffffffffu, im0, 1));
        im0 = max(im0, __shfl_xor_sync(0xffffffffu, im0, 2));
        im1 = max(im1, __shfl_xor_sync(0xffffffffu, im1, 1));
        im1 = max(im1, __shfl_xor_sync(0xffffffffu, im1, 2));
        const float mn0 = fmaxf(m0, (float)im0 * sall2);
        const float mn1 = fmaxf(m1, (float)im1 * sall2);
        const float c0 = exp2f(m0 - mn0), c1 = exp2f(m1 - mn1);
        m0 = mn0; m1 = mn1;
        l0 *= c0;  l1 *= c1;
        if (__any_sync(0xffffffffu, (c0 < 1.0f) | (c1 < 1.0f))) {
            #pragma unroll
            for (int dn = 0; dn < 16; dn++) {
                oacc[dn][0] *= c0; oacc[dn][1] *= c0;
                oacc[dn][2] *= c1; oacc[dn][3] *= c1;
            }
        }
        #pragma unroll
        for (int j = 0; j < 8; j++) {
            float e0 = exp2f(fmaf((float)sacc[j][0], sall2, -mn0));
            float e1 = exp2f(fmaf((float)sacc[j][1], sall2, -mn0));
            float e2 = exp2f(fmaf((float)sacc[j][2], sall2, -mn1));
            float e3 = exp2f(fmaf((float)sacc[j][3], sall2, -mn1));
            l0 += e0 + e1;  l1 += e2 + e3;
            const float vs0 = vsf[j*8 + ti*2];
            const float vs1 = vsf[j*8 + ti*2 + 1];
            float s0 = e0*vs0, s1 = e1*vs1, s2 = e2*vs0, s3 = e3*vs1;
            uint32_t h01 = pkf16(s1, s0);
            uint32_t h23 = pkf16(s3, s2);
            float2 f01 = __half22float2(*reinterpret_cast<__half2*>(&h01));
            float2 f23 = __half22float2(*reinterpret_cast<__half2*>(&h23));
            uint32_t r01 = pkf16(s1 - f01.y, s0 - f01.x);
            uint32_t r23 = pkf16(s3 - f23.y, s2 - f23.x);
            int kc = j >> 1, lo = (j & 1) * 2;
            pa1[kc][lo]   = h01;
            pa1[kc][lo+1] = h23;
            pa2[kc][lo]   = r01;
            pa2[kc][lo+1] = r23;
        }

        // ---- B: ensure tile it+1 arrived (and it), then QK(it+1) ----
        if (it + 2 < NTH) asm volatile("cp.async.wait_group 1;\n");
        else              asm volatile("cp.async.wait_group 0;\n");
        __syncthreads();
        if (it + 1 < NTH) do_qk((it + 1) & 1);

        // ---- D: PV(it) ----
        const uint32_t svbuf = sb + OFF_V + vb*SV_BYTES;
        #pragma unroll
        for (int kc = 0; kc < 4; kc++) {
            #pragma unroll
            for (int mI = 0; mI < 8; mI++) {
                uint32_t addr = svbuf + (uint32_t)(((kc*16 + lrow)*VSTRIDE + (2*mI + lsel)*8) * 2);
                uint32_t b0, b1, b2, b3;
                ldsm_x4_trans(addr, b0, b1, b2, b3);
                const int dn0 = 2*mI, dn1 = 2*mI + 1;
                asm volatile(
                    "mma.sync.aligned.m16n8k16.row.col.f32.f16.f16.f32 "
                    "{%0,%1,%2,%3},{%4,%5,%6,%7},{%8,%9},{%0,%1,%2,%3};\n"
                    : "+f"(oacc[dn0][0]), "+f"(oacc[dn0][1]), "+f"(oacc[dn0][2]), "+f"(oacc[dn0][3])
                    : "r"(pa1[kc][0]), "r"(pa1[kc][1]), "r"(pa1[kc][2]), "r"(pa1[kc][3]),
                      "r"(b0), "r"(b1));
                asm volatile(
                    "mma.sync.aligned.m16n8k16.row.col.f32.f16.f16.f32 "
                    "{%0,%1,%2,%3},{%4,%5,%6,%7},{%8,%9},{%0,%1,%2,%3};\n"
                    : "+f"(oacc[dn0][0]), "+f"(oacc[dn0][1]), "+f"(oacc[dn0][2]), "+f"(oacc[dn0][3])
                    : "r"(pa2[kc][0]), "r"(pa2[kc][1]), "r"(pa2[kc][2]), "r"(pa2[kc][3]),
                      "r"(b0), "r"(b1));
                asm volatile(
                    "mma.sync.aligned.m16n8k16.row.col.f32.f16.f16.f32 "
                    "{%0,%1,%2,%3},{%4,%5,%6,%7},{%8,%9},{%0,%1,%2,%3};\n"
                    : "+f"(oacc[dn1][0]), "+f"(oacc[dn1][1]), "+f"(oacc[dn1][2]), "+f"(oacc[dn1][3])
                    : "r"(pa1[kc][0]), "r"(pa1[kc][1]), "r"(pa1[kc][2]), "r"(pa1[kc][3]),
                      "r"(b2), "r"(b3));
                asm volatile(
                    "mma.sync.aligned.m16n8k16.row.col.f32.f16.f16.f32 "
                    "{%0,%1,%2,%3},{%4,%5,%6,%7},{%8,%9},{%0,%1,%2,%3};\n"
                    : "+f"(oacc[dn1][0]), "+f"(oacc[dn1][1]), "+f"(oacc[dn1][2]), "+f"(oacc[dn1][3])
                    : "r"(pa2[kc][0]), "r"(pa2[kc][1]), "r"(pa2[kc][2]), "r"(pa2[kc][3]),
                      "r"(b2), "r"(b3));
            }
        }

        // ---- tail: all warps done QK(it+1)/PV(it); next head may overwrite ----
        __syncthreads();
        vb = (vb == 2) ? 0 : vb + 1;
    }

    // -------- epilogue: write split-K partials --------
    l0 += __shfl_xor_sync(0xffffffffu, l0, 1);
    l0 += __shfl_xor_sync(0xffffffffu, l0, 2);
    l1 += __shfl_xor_sync(0xffffffffu, l1, 1);
    l1 += __shfl_xor_sync(0xffffffffu, l1, 2);
    const int r0 = qt*64 + warp*16 + gi;
    const int r1 = r0 + 8;
    const size_t row0 = (size_t)bh*SEQ + r0;
    const size_t row1 = (size_t)bh*SEQ + r1;
    if (ti == 0) {
        g_pm[part][row0] = m0;  g_pl[part][row0] = l0;
        g_pm[part][row1] = m1;  g_pl[part][row1] = l1;
    }
    float* o0 = g_po[part] + row0*DH;
    float* o1 = g_po[part] + row1*DH;
    #pragma unroll
    for (int dn = 0; dn < 16; dn++) {
        int col = dn*8 + ti*2;
        float2 pLo, pHi;
        pLo.x = oacc[dn][0]; pLo.y = oacc[dn][1];
        pHi.x = oacc[dn][2]; pHi.y = oacc[dn][3];
        *reinterpret_cast<float2*>(o0 + col) = pLo;
        *reinterpret_cast<float2*>(o1 + col) = pHi;
    }
}

// ================= split-K merge (4-way) =================
__global__ __launch_bounds__(256) void merge_kernel(float* __restrict__ out) {
    const size_t row = (size_t)blockIdx.x*8 + (threadIdx.x >> 5);
    const int lane = threadIdx.x & 31;
    float mm = g_pm[0][row];
    #pragma unroll
    for (int p = 1; p < NSPLIT; p++) mm = fmaxf(mm, g_pm[p][row]);
    float f[NSPLIT];
    float lsum = 0.f;
    #pragma unroll
    for (int p = 0; p < NSPLIT; p++) {
        f[p] = exp2f(g_pm[p][row] - mm);
        lsum += g_pl[p][row] * f[p];
    }
    const float inv = 1.f / lsum;
    float4 acc = make_float4(0.f, 0.f, 0.f, 0.f);
    #pragma unroll
    for (int p = 0; p < NSPLIT; p++) {
        const float4 a = *reinterpret_cast<const float4*>(g_po[p] + row*DH + lane*4);
        acc.x = fmaf(a.x, f[p], acc.x);
        acc.y = fmaf(a.y, f[p], acc.y);
        acc.z = fmaf(a.z, f[p], acc.z);
        acc.w = fmaf(a.w, f[p], acc.w);
    }
    float4 r;
    r.x = bf16r(acc.x * inv);
    r.y = bf16r(acc.y * inv);
    r.z = bf16r(acc.z * inv);
    r.w = bf16r(acc.w * inv);
    *reinterpret_cast<float4*>(out + row*DH + lane*4) = r;
}

// ---------------- launch ----------------
extern "C" void kernel_launch(void* const* d_in, const int* in_sizes, int n_in,
                              void* d_out, int out_size) {
    const float* q = (const float*)d_in[0];
    const float* k = (const float*)d_in[1];
    const float* v = (const float*)d_in[2];
    float* out = (float*)d_out;

    static int attr_set = 0;
    if (!attr_set) {
        cudaFuncSetAttribute(attn_kernel, cudaFuncAttributeMaxDynamicSharedMemorySize, SMEM_TOT);
        attr_set = 1;
    }

    nq_pre<<<BHN*NQB + BHN*256 + BHN*16, 256>>>(q, v, k);
    nq_quant_k<<<BHN*NKB, 128>>>(k);
    attn_kernel<<<BHN*NQB*NSPLIT, 128, SMEM_TOT>>>();
    merge_kernel<<<(BHN*SEQ)/8, 256>>>(out);
}